// round 14
// baseline (speedup 1.0000x reference)
#include <cuda_runtime.h>
#include <math.h>

// ---------------- problem constants (static in reference) ----------------
#define N_SAMPLES 4410000
#define WSZ       441          // wavetable size
#define BB        80           // chunks per block
#define GG        125          // worker blocks (BB*GG == 10000 chunks)
#define KH        8            // recurrence steps per barrier (halo depth)
#define NG        (BB / KH)    // 10 barrier groups
#define R21       21           // radix (441 = 21*21)

#define PI_F      3.14159265358979f
#define TWOPI_F   6.2831853071795864f
#define SR_F      44100.0f

// ---------------- device scratch / sync ----------------------------------
__device__ float g_Ehat[GG * 2 * WSZ]; // per-block forced end-state spectra
__device__ float g_what[2 * WSZ];      // wavetable spectrum (from setup CTA)
__device__ int   g_flags[GG + 1];      // epoch flags (monotone across launches)

// ---------------- parallel biquad via affine scan ------------------------
__device__ void biquad_par(const float* __restrict__ x, float* __restrict__ y,
                           float f, float q, int tid,
                           float* sb1, float* sb2, float (*sMp)[4]) {
    float w0   = (TWOPI_F * f) / SR_F;
    float cosw = cosf(w0);
    float alpha = sinf(w0) / (2.0f * q);
    float b0 = (1.0f - cosw) / 2.0f;
    float b1c = 1.0f - cosw;
    float b2c = (1.0f - cosw) / 2.0f;
    float a0 = 1.0f + alpha;
    float a1 = -2.0f * cosw;
    float a2 = 1.0f - alpha;
    b0 /= a0; b1c /= a0; b2c /= a0; a1 /= a0; a2 /= a0;
    float d1 = b1c - a1 * b0;
    float d2 = b2c - a2 * b0;

    if (tid == 0) {
        float A0 = -a1, A1 = 1.0f, A2 = -a2, A3 = 0.0f;
        #pragma unroll
        for (int dd = 0; dd < 9; dd++) {
            sMp[dd][0] = A0; sMp[dd][1] = A1; sMp[dd][2] = A2; sMp[dd][3] = A3;
            float n0 = A0 * A0 + A1 * A2;
            float n1 = A0 * A1 + A1 * A3;
            float n2 = A2 * A0 + A3 * A2;
            float n3 = A2 * A1 + A3 * A3;
            A0 = n0; A1 = n1; A2 = n2; A3 = n3;
        }
    }
    float xv = x[tid];
    sb1[tid] = xv * d1;
    sb2[tid] = xv * d2;
    __syncthreads();
    #pragma unroll
    for (int dd = 0; dd < 9; dd++) {
        int off = 1 << dd;
        float p1 = 0.0f, p2 = 0.0f;
        if (tid >= off) { p1 = sb1[tid - off]; p2 = sb2[tid - off]; }
        float m0 = sMp[dd][0], m1 = sMp[dd][1], m2 = sMp[dd][2], m3 = sMp[dd][3];
        __syncthreads();
        if (tid >= off) {
            sb1[tid] = fmaf(m0, p1, fmaf(m1, p2, sb1[tid]));
            sb2[tid] = fmaf(m2, p1, fmaf(m3, p2, sb2[tid]));
        }
        __syncthreads();
    }
    float s1 = (tid == 0) ? 0.0f : sb1[tid - 1];
    y[tid] = fmaf(b0, xv, s1);
    __syncthreads();
}

// ---------------- radix-21 forward DFT (smem -> per-thread register bin) --
__device__ __forceinline__ void dft441_fwd_reg(const float* __restrict__ sx,
                                               float* __restrict__ t_re,
                                               float* __restrict__ t_im,
                                               int tid, float* oRe, float* oIm) {
    {   // stage 1: tid = mmod*21 + i0
        int mmod = tid / R21, i0 = tid % R21;
        float ang = -TWOPI_F * (float)mmod / 21.0f;
        float c0, s0; sincosf(ang, &s0, &c0);
        float wc = 1.0f, ws = 0.0f, re = 0.0f, im = 0.0f;
        #pragma unroll
        for (int i1 = 0; i1 < R21; i1++) {
            float v = sx[i0 + R21 * i1];
            re = fmaf(v, wc, re);
            im = fmaf(v, ws, im);
            float nw = wc * c0 - ws * s0;
            ws = fmaf(wc, s0, ws * c0);
            wc = nw;
        }
        t_re[tid] = re; t_im[tid] = im;
    }
    __syncthreads();
    {   // stage 2: tid = m
        int m = tid, mm = m % R21;
        float ang = -TWOPI_F * (float)m / 441.0f;
        float c0, s0; sincosf(ang, &s0, &c0);
        float wc = 1.0f, ws = 0.0f, re = 0.0f, im = 0.0f;
        const float* gr = t_re + mm * R21;
        const float* gi = t_im + mm * R21;
        #pragma unroll
        for (int i0 = 0; i0 < R21; i0++) {
            float a = gr[i0], b = gi[i0];
            re = fmaf(a, wc, fmaf(-b, ws, re));
            im = fmaf(a, ws, fmaf( b, wc, im));
            float nw = wc * c0 - ws * s0;
            ws = fmaf(wc, s0, ws * c0);
            wc = nw;
        }
        *oRe = re; *oIm = im;
    }
    __syncthreads();   // callers reuse the temps after this
}

// ---------------- tiny MLP: all CTAs (cheap; yields decay/fa/etc) ---------
__device__ __forceinline__ void mlp_latents(const float* __restrict__ h,
                                            const float* __restrict__ W1,
                                            const float* __restrict__ b1,
                                            const float* __restrict__ W2,
                                            const float* __restrict__ b2,
                                            float* shid, float* slat, int tid) {
    if (tid < 128) {
        float acc = b1[tid];
        #pragma unroll
        for (int i = 0; i < 9; i++) acc += h[i] * W1[i * 128 + tid];
        shid[tid] = fmaxf(acc, 0.0f);
    }
    __syncthreads();
    if (tid < 160) {   // 5 outputs x 32-lane shfl reduce
        int o = tid >> 5, j0 = tid & 31;
        float acc = 0.0f;
        #pragma unroll
        for (int r = 0; r < 4; r++) {
            int j = j0 + 32 * r;
            acc = fmaf(shid[j], W2[j * 5 + o], acc);
        }
        #pragma unroll
        for (int off = 16; off > 0; off >>= 1)
            acc += __shfl_down_sync(0xffffffffu, acc, off);
        if (j0 == 0) slat[o] = fmaxf(acc + b2[o], 0.0f);
    }
    __syncthreads();
}

// ---------------- the single fused kernel (GG workers + 1 setup CTA) ------
__global__ __launch_bounds__(WSZ, 1)
void k_fused(const float* __restrict__ fb,    const float* __restrict__ h,
             const float* __restrict__ noise, const float* __restrict__ W1,
             const float* __restrict__ b1,    const float* __restrict__ W2,
             const float* __restrict__ b2,    const float* __restrict__ lp,
             const float* __restrict__ env,   const float* __restrict__ fade,
             float* __restrict__ out) {
    extern __shared__ float smx[];
    float* sfb = smx;                  // BB*WSZ (fb tile; pass A overwrites with forced rows)
    float* aux = smx + BB * WSZ;       // 6*WSZ scratch
    __shared__ int s_epoch;

    int tid = threadIdx.x;
    int g   = blockIdx.x;

    if (tid == 0) s_epoch = ((volatile int*)g_flags)[g];

    float* sx   = aux;
    float* sy   = aux + WSZ;
    float* sb1  = aux + 2 * WSZ;
    float* sb2  = aux + 3 * WSZ;
    float* shid = aux + 4 * WSZ;          // 128
    float* slat = aux + 4 * WSZ + 128;    // 5
    float (*sMp)[4] = (float(*)[4])(aux + 4 * WSZ + 160); // 36

    // ================= setup CTA (g == GG): biquads + What, publish ======
    if (g == GG) {
        mlp_latents(h, W1, b1, W2, b2, shid, slat, tid);
        float lpf = fminf(fmaxf(slat[1] * SR_F / 4.0f, 100.0f), SR_F / 2.0f - 1.0f);
        float lpq = fminf(fmaxf(slat[2], 0.1f), 0.999f);
        sx[tid] = noise[tid];
        __syncthreads();
        biquad_par(sx, sy, lpf, lpq, tid, sb1, sb2, sMp);
        biquad_par(sy, sx, lp[0], 0.707f, tid, sb1, sb2, sMp);
        float Wre, Wim;
        dft441_fwd_reg(sx, sb1, sb2, tid, &Wre, &Wim);
        ((float2*)g_what)[tid] = make_float2(Wre, Wim);
        __threadfence();
        __syncthreads();
        if (tid == 0) ((volatile int*)g_flags)[GG] = s_epoch + 1;
        return;
    }

    // ================= worker CTAs (g < GG) ==============================
    // stage fb tile as float4 (BB*WSZ = 8820 float4)
    {
        const float4* f4 = (const float4*)(fb + (size_t)g * BB * WSZ);
        float4* s4 = (float4*)sfb;
        #pragma unroll
        for (int k = 0; k < 20; k++) s4[tid + WSZ * k] = f4[tid + WSZ * k];
    }

    mlp_latents(h, W1, b1, W2, b2, shid, slat, tid);

    float decay = fminf(fmaxf(slat[0] / 10.0f + 0.9f, 0.9f), 0.999f);
    float c    = decay * 0.5f;
    float fa   = slat[3];
    float inva = 1.0f / (fabsf(env[0]) + 1e-3f);
    float sA   = env[1] * slat[4];
    float invr = 1.0f / (fabsf(env[2]) + 1e-3f);
    float T    = (float)(N_SAMPLES - 1) / SR_F;   // == t[-1] exactly in fp32

    // lambda^BB (bin tid) in registers
    float Lre, Lim;
    {
        float rr  = decay * cosf((PI_F * (float)tid) / 441.0f);
        float mag = powf(fabsf(rr), (float)BB);   // BB even -> sign drops
        int   k2  = (BB * tid) % (2 * WSZ);
        float angp = -(PI_F * (float)k2) / 441.0f;
        float sp, cp; sincosf(angp, &sp, &cp);
        Lre = mag * cp; Lim = mag * sp;
    }

    int i = tid;
    int iw[KH + 1];
    #pragma unroll
    for (int m = 0; m <= KH; m++) { int v = i - m; if (v < 0) v += WSZ; iw[m] = v; }

    // ---- pass A: forced response from zero; overwrite consumed fb rows ----
    float* ob = aux;                   // 2*WSZ double buffer (sx/sy region)
    ob[tid] = 0.0f;
    int cb = 0;
    __syncthreads();

    for (int grp = 0; grp < NG; grp++) {
        int b = grp * KH;
        float O[KH + 1], X[KH + 1], Fout[KH];
        const float* obr = ob + cb * WSZ;
        #pragma unroll
        for (int m = 0; m <= KH; m++) O[m] = obr[iw[KH - m]];
        #pragma unroll
        for (int j = 0; j < KH; j++) {
            const float* fr = sfb + (b + j) * WSZ;
            #pragma unroll
            for (int m = j; m <= KH; m++) X[m] = fmaf(fa, fr[iw[KH - m]], O[m]);
            #pragma unroll
            for (int m = KH; m > j; m--) O[m] = c * (X[m] + X[m - 1]);
            Fout[j] = O[KH];
        }
        ob[(cb ^ 1) * WSZ + i] = O[KH];
        __syncthreads();
        // rows b..b+KH-1 fully consumed by all threads -> overwrite in smem
        #pragma unroll
        for (int j = 0; j < KH; j++) sfb[(b + j) * WSZ + i] = Fout[j];
        cb ^= 1;
    }

    // ---- forward DFT of forced end state -> publish g_Ehat[g] + flag ----
    {
        float Ere, Eim;
        dft441_fwd_reg(ob + cb * WSZ, aux + 2 * WSZ, aux + 3 * WSZ, tid, &Ere, &Eim);
        ((float2*)(g_Ehat + (size_t)g * 2 * WSZ))[tid] = make_float2(Ere, Eim);
    }
    __threadfence();          // my Ehat writes visible device-wide
    __syncthreads();
    if (tid == 0) ((volatile int*)g_flags)[g] = s_epoch + 1;

    // ---- PARALLEL wait: thread t polls flags[t] (t<g); thread 440 polls
    //      the setup flag.  Never waits on a later CTA; all 126 CTAs are
    //      co-resident (1 CTA/SM, 126 <= 148) -> deadlock-free. ----
    {
        int need = s_epoch + 1;
        if (tid < g) {
            if (((volatile int*)g_flags)[tid] < need)          // fast path: 1 load
                while (((volatile int*)g_flags)[tid] < need) __nanosleep(64);
        }
        if (tid == WSZ - 1) {
            if (((volatile int*)g_flags)[GG] < need)
                while (((volatile int*)g_flags)[GG] < need) __nanosleep(64);
        }
    }
    __syncthreads();
    __threadfence();          // acquire side

    // ---- per-CTA spectral scan: S = What; for g'<g: S = L*S + Ehat[g'] ----
    float* sre = aux + 2 * WSZ;
    float* sim = aux + 3 * WSZ;
    float* Hre = aux + 4 * WSZ;
    float* Him = aux + 5 * WSZ;
    {
        float2 Wv = ((const float2*)g_what)[tid];
        float Sre = Wv.x, Sim = Wv.y;
        const float2* Eh = (const float2*)g_Ehat;
        #pragma unroll 8
        for (int gp = 0; gp < g; gp++) {
            float2 E = Eh[gp * WSZ + tid];
            float nre = fmaf(Lre, Sre, fmaf(-Lim, Sim, E.x));
            float nim = fmaf(Lre, Sim, fmaf( Lim, Sre, E.y));
            Sre = nre; Sim = nim;
        }
        sre[tid] = Sre; sim[tid] = Sim;
    }
    __syncthreads();

    // ---- inverse DFT (radix-21): x[i] = (1/441) Re{ sum_m S[m] e^{+..} } ----
    {   // stage 1: tid = m0*21 + imod
        int m0 = tid / R21, imod = tid % R21;
        float ang = TWOPI_F * (float)imod / 21.0f;
        float c0, s0; sincosf(ang, &s0, &c0);
        float wc = 1.0f, ws = 0.0f, hre = 0.0f, him = 0.0f;
        #pragma unroll
        for (int m1 = 0; m1 < R21; m1++) {
            float a = sre[m0 + R21 * m1];
            float b = sim[m0 + R21 * m1];
            hre = fmaf(a, wc, fmaf(-b, ws, hre));
            him = fmaf(a, ws, fmaf( b, wc, him));
            float nw = wc * c0 - ws * s0;
            ws = fmaf(wc, s0, ws * c0);
            wc = nw;
        }
        Hre[tid] = hre; Him[tid] = him;
    }
    __syncthreads();
    {   // stage 2: tid = i (real part only)
        int im21 = i % R21;
        float ang = TWOPI_F * (float)i / 441.0f;
        float c0, s0; sincosf(ang, &s0, &c0);
        float wc = 1.0f, ws = 0.0f, acc = 0.0f;
        #pragma unroll
        for (int m0 = 0; m0 < R21; m0++) {
            float a = Hre[m0 * R21 + im21];
            float b = Him[m0 * R21 + im21];
            acc = fmaf(a, wc, fmaf(-b, ws, acc));
            float nw = wc * c0 - ws * s0;
            ws = fmaf(wc, s0, ws * c0);
            wc = nw;
        }
        ob[i] = acc * (1.0f / 441.0f);
    }
    cb = 0;
    __syncthreads();

    // ---- pass B: homogeneous recurrence; out = homog + forced(smem) ----
    int n = g * BB * WSZ + i;
    float tn = (float)n * (1.0f / SR_F);
    const float dtn = (float)WSZ * (1.0f / SR_F);
    for (int grp = 0; grp < NG; grp++) {
        int b = grp * KH;
        float O[KH + 1], Fc[KH];
        const float* obr = ob + cb * WSZ;
        #pragma unroll
        for (int m = 0; m <= KH; m++) O[m] = obr[iw[KH - m]];
        #pragma unroll
        for (int j = 0; j < KH; j++) Fc[j] = sfb[(b + j) * WSZ + i];
        #pragma unroll
        for (int j = 0; j < KH; j++) {
            #pragma unroll
            for (int m = KH; m > j; m--) O[m] = c * (O[m] + O[m - 1]);

            float v = O[KH] + Fc[j];
            if (n >= N_SAMPLES - 256) v *= fade[n - (N_SAMPLES - 256)];
            float e1 = __saturatef(tn * inva);
            float e2 = __saturatef((T - tn) * invr);
            out[n] = v * (e1 * e2) * sA;
            n += WSZ;
            tn += dtn;
        }
        ob[(cb ^ 1) * WSZ + i] = O[KH];
        __syncthreads();
        cb ^= 1;
    }
}

// ---------------- host entry --------------------------------------------
extern "C" void kernel_launch(void* const* d_in, const int* in_sizes, int n_in,
                              void* d_out, int out_size) {
    const float* fb    = (const float*)d_in[0];   // feedback_line [4410000]
    const float* h     = (const float*)d_in[1];   // h [1,9]
    // d_in[2] = t — unused (t[n] == n/44100 exactly in fp32)
    const float* noise = (const float*)d_in[3];   // wavetable_noise [441]
    const float* W1    = (const float*)d_in[4];   // [9,128]
    const float* b1    = (const float*)d_in[5];   // [128]
    const float* W2    = (const float*)d_in[6];   // [128,5]
    const float* b2    = (const float*)d_in[7];   // [5]
    const float* lp    = (const float*)d_in[8];   // lp_cutoff [1]
    const float* env   = (const float*)d_in[9];   // env_params [3]
    const float* fade  = (const float*)d_in[10];  // fade [256]
    float* out = (float*)d_out;

    const int ds = (BB * WSZ + 6 * WSZ) * (int)sizeof(float);  // 151,704 B
    cudaFuncSetAttribute(k_fused, cudaFuncAttributeMaxDynamicSharedMemorySize, ds);

    k_fused<<<GG + 1, WSZ, ds>>>(fb, h, noise, W1, b1, W2, b2, lp, env, fade, out);
}

// round 15
// speedup vs baseline: 1.1011x; 1.1011x over previous
#include <cuda_runtime.h>
#include <math.h>

// ---------------- problem constants (static in reference) ----------------
#define N_SAMPLES 4410000
#define WSZ       441          // wavetable size
#define BB        80           // chunks per block
#define GG        125          // worker blocks (BB*GG == 10000 chunks)
#define KH        4            // recurrence steps per barrier (halo depth)
#define NG        (BB / KH)    // 20 barrier groups
#define R21       21           // radix (441 = 21*21)

#define PI_F      3.14159265358979f
#define TWOPI_F   6.2831853071795864f
#define SR_F      44100.0f

// ---------------- device scratch / sync ----------------------------------
__device__ float g_Ehat[GG * 2 * WSZ]; // per-block forced end-state spectra
__device__ float g_what[2 * WSZ];      // wavetable spectrum (from setup CTA)
__device__ int   g_flags[GG + 1];      // epoch flags (monotone across launches)

// ---------------- parallel biquad via affine scan ------------------------
// (coefficient math stays in accurate libm: runs once, on the setup CTA only)
__device__ void biquad_par(const float* __restrict__ x, float* __restrict__ y,
                           float f, float q, int tid,
                           float* sb1, float* sb2, float (*sMp)[4]) {
    float w0   = (TWOPI_F * f) / SR_F;
    float cosw = cosf(w0);
    float alpha = sinf(w0) / (2.0f * q);
    float b0 = (1.0f - cosw) / 2.0f;
    float b1c = 1.0f - cosw;
    float b2c = (1.0f - cosw) / 2.0f;
    float a0 = 1.0f + alpha;
    float a1 = -2.0f * cosw;
    float a2 = 1.0f - alpha;
    b0 /= a0; b1c /= a0; b2c /= a0; a1 /= a0; a2 /= a0;
    float d1 = b1c - a1 * b0;
    float d2 = b2c - a2 * b0;

    if (tid == 0) {
        float A0 = -a1, A1 = 1.0f, A2 = -a2, A3 = 0.0f;
        #pragma unroll
        for (int dd = 0; dd < 9; dd++) {
            sMp[dd][0] = A0; sMp[dd][1] = A1; sMp[dd][2] = A2; sMp[dd][3] = A3;
            float n0 = A0 * A0 + A1 * A2;
            float n1 = A0 * A1 + A1 * A3;
            float n2 = A2 * A0 + A3 * A2;
            float n3 = A2 * A1 + A3 * A3;
            A0 = n0; A1 = n1; A2 = n2; A3 = n3;
        }
    }
    float xv = x[tid];
    sb1[tid] = xv * d1;
    sb2[tid] = xv * d2;
    __syncthreads();
    #pragma unroll
    for (int dd = 0; dd < 9; dd++) {
        int off = 1 << dd;
        float p1 = 0.0f, p2 = 0.0f;
        if (tid >= off) { p1 = sb1[tid - off]; p2 = sb2[tid - off]; }
        float m0 = sMp[dd][0], m1 = sMp[dd][1], m2 = sMp[dd][2], m3 = sMp[dd][3];
        __syncthreads();
        if (tid >= off) {
            sb1[tid] = fmaf(m0, p1, fmaf(m1, p2, sb1[tid]));
            sb2[tid] = fmaf(m2, p1, fmaf(m3, p2, sb2[tid]));
        }
        __syncthreads();
    }
    float s1 = (tid == 0) ? 0.0f : sb1[tid - 1];
    y[tid] = fmaf(b0, xv, s1);
    __syncthreads();
}

// ---------------- radix-21 forward DFT (smem -> per-thread register bin) --
// Twiddles via fast-math __sincosf (args within ±2*pi; err ~1e-6 << 1e-3 tol)
__device__ __forceinline__ void dft441_fwd_reg(const float* __restrict__ sx,
                                               float* __restrict__ t_re,
                                               float* __restrict__ t_im,
                                               int tid, float* oRe, float* oIm) {
    {   // stage 1: tid = mmod*21 + i0
        int mmod = tid / R21, i0 = tid % R21;
        float ang = -TWOPI_F * (float)mmod / 21.0f;
        float c0, s0; __sincosf(ang, &s0, &c0);
        float wc = 1.0f, ws = 0.0f, re = 0.0f, im = 0.0f;
        #pragma unroll
        for (int i1 = 0; i1 < R21; i1++) {
            float v = sx[i0 + R21 * i1];
            re = fmaf(v, wc, re);
            im = fmaf(v, ws, im);
            float nw = wc * c0 - ws * s0;
            ws = fmaf(wc, s0, ws * c0);
            wc = nw;
        }
        t_re[tid] = re; t_im[tid] = im;
    }
    __syncthreads();
    {   // stage 2: tid = m
        int m = tid, mm = m % R21;
        float ang = -TWOPI_F * (float)m / 441.0f;
        float c0, s0; __sincosf(ang, &s0, &c0);
        float wc = 1.0f, ws = 0.0f, re = 0.0f, im = 0.0f;
        const float* gr = t_re + mm * R21;
        const float* gi = t_im + mm * R21;
        #pragma unroll
        for (int i0 = 0; i0 < R21; i0++) {
            float a = gr[i0], b = gi[i0];
            re = fmaf(a, wc, fmaf(-b, ws, re));
            im = fmaf(a, ws, fmaf( b, wc, im));
            float nw = wc * c0 - ws * s0;
            ws = fmaf(wc, s0, ws * c0);
            wc = nw;
        }
        *oRe = re; *oIm = im;
    }
    __syncthreads();   // callers reuse the temps after this
}

// ---------------- tiny MLP: all CTAs (cheap; yields decay/fa/etc) ---------
__device__ __forceinline__ void mlp_latents(const float* __restrict__ h,
                                            const float* __restrict__ W1,
                                            const float* __restrict__ b1,
                                            const float* __restrict__ W2,
                                            const float* __restrict__ b2,
                                            float* shid, float* slat, int tid) {
    if (tid < 128) {
        float acc = b1[tid];
        #pragma unroll
        for (int i = 0; i < 9; i++) acc += h[i] * W1[i * 128 + tid];
        shid[tid] = fmaxf(acc, 0.0f);
    }
    __syncthreads();
    if (tid < 160) {   // 5 outputs x 32-lane shfl reduce
        int o = tid >> 5, j0 = tid & 31;
        float acc = 0.0f;
        #pragma unroll
        for (int r = 0; r < 4; r++) {
            int j = j0 + 32 * r;
            acc = fmaf(shid[j], W2[j * 5 + o], acc);
        }
        #pragma unroll
        for (int off = 16; off > 0; off >>= 1)
            acc += __shfl_down_sync(0xffffffffu, acc, off);
        if (j0 == 0) slat[o] = fmaxf(acc + b2[o], 0.0f);
    }
    __syncthreads();
}

// ---------------- the single fused kernel (GG workers + 1 setup CTA) ------
__global__ __launch_bounds__(WSZ, 1)
void k_fused(const float* __restrict__ fb,    const float* __restrict__ h,
             const float* __restrict__ noise, const float* __restrict__ W1,
             const float* __restrict__ b1,    const float* __restrict__ W2,
             const float* __restrict__ b2,    const float* __restrict__ lp,
             const float* __restrict__ env,   const float* __restrict__ fade,
             float* __restrict__ out) {
    extern __shared__ float smx[];
    float* sfb = smx;                  // BB*WSZ (fb tile; pass A overwrites with forced rows)
    float* aux = smx + BB * WSZ;       // 6*WSZ scratch
    __shared__ int s_epoch;

    int tid = threadIdx.x;
    int g   = blockIdx.x;

    if (tid == 0) s_epoch = ((volatile int*)g_flags)[g];

    float* sx   = aux;
    float* sy   = aux + WSZ;
    float* sb1  = aux + 2 * WSZ;
    float* sb2  = aux + 3 * WSZ;
    float* shid = aux + 4 * WSZ;          // 128
    float* slat = aux + 4 * WSZ + 128;    // 5
    float (*sMp)[4] = (float(*)[4])(aux + 4 * WSZ + 160); // 36

    // ================= setup CTA (g == GG): biquads + What, publish ======
    if (g == GG) {
        mlp_latents(h, W1, b1, W2, b2, shid, slat, tid);
        float lpf = fminf(fmaxf(slat[1] * SR_F / 4.0f, 100.0f), SR_F / 2.0f - 1.0f);
        float lpq = fminf(fmaxf(slat[2], 0.1f), 0.999f);
        sx[tid] = noise[tid];
        __syncthreads();
        biquad_par(sx, sy, lpf, lpq, tid, sb1, sb2, sMp);
        biquad_par(sy, sx, lp[0], 0.707f, tid, sb1, sb2, sMp);
        float Wre, Wim;
        dft441_fwd_reg(sx, sb1, sb2, tid, &Wre, &Wim);
        ((float2*)g_what)[tid] = make_float2(Wre, Wim);
        __threadfence();
        __syncthreads();
        if (tid == 0) ((volatile int*)g_flags)[GG] = s_epoch + 1;
        return;
    }

    // ================= worker CTAs (g < GG) ==============================
    // stage fb tile as float4 (BB*WSZ = 8820 float4)
    {
        const float4* f4 = (const float4*)(fb + (size_t)g * BB * WSZ);
        float4* s4 = (float4*)sfb;
        #pragma unroll
        for (int k = 0; k < 20; k++) s4[tid + WSZ * k] = f4[tid + WSZ * k];
    }

    mlp_latents(h, W1, b1, W2, b2, shid, slat, tid);

    float decay = fminf(fmaxf(slat[0] / 10.0f + 0.9f, 0.9f), 0.999f);
    float c    = decay * 0.5f;
    float fa   = slat[3];
    float inva = 1.0f / (fabsf(env[0]) + 1e-3f);
    float sA   = env[1] * slat[4];
    float invr = 1.0f / (fabsf(env[2]) + 1e-3f);
    float T    = (float)(N_SAMPLES - 1) / SR_F;   // == t[-1] exactly in fp32

    int i = tid;
    int iw[KH + 1];
    #pragma unroll
    for (int m = 0; m <= KH; m++) { int v = i - m; if (v < 0) v += WSZ; iw[m] = v; }

    // ---- pass A: forced response from zero; overwrite consumed fb rows ----
    float* ob = aux;                   // 2*WSZ double buffer (sx/sy region)
    ob[tid] = 0.0f;
    int cb = 0;
    __syncthreads();

    for (int grp = 0; grp < NG; grp++) {
        int b = grp * KH;
        float O[KH + 1], X[KH + 1], Fout[KH];
        float Fv[KH][KH + 1];
        const float* obr = ob + cb * WSZ;
        // batch-preload: all independent LDS issue before the dependent chain
        #pragma unroll
        for (int m = 0; m <= KH; m++) O[m] = obr[iw[KH - m]];
        #pragma unroll
        for (int j = 0; j < KH; j++) {
            const float* fr = sfb + (b + j) * WSZ;
            #pragma unroll
            for (int m = j; m <= KH; m++) Fv[j][m] = fr[iw[KH - m]];
        }
        #pragma unroll
        for (int j = 0; j < KH; j++) {
            #pragma unroll
            for (int m = j; m <= KH; m++) X[m] = fmaf(fa, Fv[j][m], O[m]);
            #pragma unroll
            for (int m = KH; m > j; m--) O[m] = c * (X[m] + X[m - 1]);
            Fout[j] = O[KH];
        }
        ob[(cb ^ 1) * WSZ + i] = O[KH];
        __syncthreads();
        // rows b..b+KH-1 fully consumed by all threads -> overwrite in smem
        #pragma unroll
        for (int j = 0; j < KH; j++) sfb[(b + j) * WSZ + i] = Fout[j];
        cb ^= 1;
    }

    // ---- forward DFT of forced end state -> publish g_Ehat[g] + flag ----
    {
        float Ere, Eim;
        dft441_fwd_reg(ob + cb * WSZ, aux + 2 * WSZ, aux + 3 * WSZ, tid, &Ere, &Eim);
        ((float2*)(g_Ehat + (size_t)g * 2 * WSZ))[tid] = make_float2(Ere, Eim);
    }
    __threadfence();          // my Ehat writes visible device-wide
    __syncthreads();
    if (tid == 0) ((volatile int*)g_flags)[g] = s_epoch + 1;

    // ---- lambda^BB (bin tid): computed AFTER publish, overlaps the wait ----
    float Lre, Lim;
    {
        float rr  = decay * __cosf((PI_F * (float)tid) / 441.0f);
        float ar  = fabsf(rr);
        float r2  = ar * ar;            // ^2
        float r4  = r2 * r2;            // ^4
        float r5  = r4 * ar;            // ^5
        float r10 = r5 * r5;            // ^10
        float r20 = r10 * r10;          // ^20
        float r40 = r20 * r20;          // ^40
        float mag = r40 * r40;          // ^80  (BB even -> sign drops)
        int   k2  = (BB * tid) % (2 * WSZ);
        float angp = -(PI_F * (float)k2) / 441.0f;
        float sp, cp; __sincosf(angp, &sp, &cp);
        Lre = mag * cp; Lim = mag * sp;
    }

    // ---- PARALLEL wait: thread t polls flags[t] (t<g); thread 440 polls
    //      the setup flag.  Never waits on a later CTA; all 126 CTAs are
    //      co-resident (1 CTA/SM, 126 <= 148) -> deadlock-free. ----
    {
        int need = s_epoch + 1;
        if (tid < g) {
            if (((volatile int*)g_flags)[tid] < need)          // fast path: 1 load
                while (((volatile int*)g_flags)[tid] < need) __nanosleep(64);
        }
        if (tid == WSZ - 1) {
            if (((volatile int*)g_flags)[GG] < need)
                while (((volatile int*)g_flags)[GG] < need) __nanosleep(64);
        }
    }
    __syncthreads();
    __threadfence();          // acquire side

    // ---- per-CTA spectral scan: S = What; for g'<g: S = L*S + Ehat[g'] ----
    float* sre = aux + 2 * WSZ;
    float* sim = aux + 3 * WSZ;
    float* Hre = aux + 4 * WSZ;
    float* Him = aux + 5 * WSZ;
    {
        float2 Wv = ((const float2*)g_what)[tid];
        float Sre = Wv.x, Sim = Wv.y;
        const float2* Eh = (const float2*)g_Ehat;
        #pragma unroll 8
        for (int gp = 0; gp < g; gp++) {
            float2 E = Eh[gp * WSZ + tid];
            float nre = fmaf(Lre, Sre, fmaf(-Lim, Sim, E.x));
            float nim = fmaf(Lre, Sim, fmaf( Lim, Sre, E.y));
            Sre = nre; Sim = nim;
        }
        sre[tid] = Sre; sim[tid] = Sim;
    }
    __syncthreads();

    // ---- inverse DFT (radix-21): x[i] = (1/441) Re{ sum_m S[m] e^{+..} } ----
    {   // stage 1: tid = m0*21 + imod
        int m0 = tid / R21, imod = tid % R21;
        float ang = TWOPI_F * (float)imod / 21.0f;
        float c0, s0; __sincosf(ang, &s0, &c0);
        float wc = 1.0f, ws = 0.0f, hre = 0.0f, him = 0.0f;
        #pragma unroll
        for (int m1 = 0; m1 < R21; m1++) {
            float a = sre[m0 + R21 * m1];
            float b = sim[m0 + R21 * m1];
            hre = fmaf(a, wc, fmaf(-b, ws, hre));
            him = fmaf(a, ws, fmaf( b, wc, him));
            float nw = wc * c0 - ws * s0;
            ws = fmaf(wc, s0, ws * c0);
            wc = nw;
        }
        Hre[tid] = hre; Him[tid] = him;
    }
    __syncthreads();
    {   // stage 2: tid = i (real part only)
        int im21 = i % R21;
        float ang = TWOPI_F * (float)i / 441.0f;
        float c0, s0; __sincosf(ang, &s0, &c0);
        float wc = 1.0f, ws = 0.0f, acc = 0.0f;
        #pragma unroll
        for (int m0 = 0; m0 < R21; m0++) {
            float a = Hre[m0 * R21 + im21];
            float b = Him[m0 * R21 + im21];
            acc = fmaf(a, wc, fmaf(-b, ws, acc));
            float nw = wc * c0 - ws * s0;
            ws = fmaf(wc, s0, ws * c0);
            wc = nw;
        }
        ob[i] = acc * (1.0f / 441.0f);
    }
    cb = 0;
    __syncthreads();

    // ---- pass B: homogeneous recurrence; out = homog + forced(smem) ----
    int n = g * BB * WSZ + i;
    float tn = (float)n * (1.0f / SR_F);
    const float dtn = (float)WSZ * (1.0f / SR_F);
    for (int grp = 0; grp < NG; grp++) {
        int b = grp * KH;
        float O[KH + 1], Fc[KH];
        const float* obr = ob + cb * WSZ;
        // batch-preload the halo state + forced values (independent LDS)
        #pragma unroll
        for (int m = 0; m <= KH; m++) O[m] = obr[iw[KH - m]];
        #pragma unroll
        for (int j = 0; j < KH; j++) Fc[j] = sfb[(b + j) * WSZ + i];
        #pragma unroll
        for (int j = 0; j < KH; j++) {
            #pragma unroll
            for (int m = KH; m > j; m--) O[m] = c * (O[m] + O[m - 1]);

            float v = O[KH] + Fc[j];
            if (n >= N_SAMPLES - 256) v *= fade[n - (N_SAMPLES - 256)];
            float e1 = __saturatef(tn * inva);
            float e2 = __saturatef((T - tn) * invr);
            out[n] = v * (e1 * e2) * sA;
            n += WSZ;
            tn += dtn;
        }
        ob[(cb ^ 1) * WSZ + i] = O[KH];
        __syncthreads();
        cb ^= 1;
    }
}

// ---------------- host entry --------------------------------------------
extern "C" void kernel_launch(void* const* d_in, const int* in_sizes, int n_in,
                              void* d_out, int out_size) {
    const float* fb    = (const float*)d_in[0];   // feedback_line [4410000]
    const float* h     = (const float*)d_in[1];   // h [1,9]
    // d_in[2] = t — unused (t[n] == n/44100 exactly in fp32)
    const float* noise = (const float*)d_in[3];   // wavetable_noise [441]
    const float* W1    = (const float*)d_in[4];   // [9,128]
    const float* b1    = (const float*)d_in[5];   // [128]
    const float* W2    = (const float*)d_in[6];   // [128,5]
    const float* b2    = (const float*)d_in[7];   // [5]
    const float* lp    = (const float*)d_in[8];   // lp_cutoff [1]
    const float* env   = (const float*)d_in[9];   // env_params [3]
    const float* fade  = (const float*)d_in[10];  // fade [256]
    float* out = (float*)d_out;

    const int ds = (BB * WSZ + 6 * WSZ) * (int)sizeof(float);  // 151,704 B
    cudaFuncSetAttribute(k_fused, cudaFuncAttributeMaxDynamicSharedMemorySize, ds);

    k_fused<<<GG + 1, WSZ, ds>>>(fb, h, noise, W1, b1, W2, b2, lp, env, fade, out);
}